// round 6
// baseline (speedup 1.0000x reference)
#include <cuda_runtime.h>
#include <cuda_bf16.h>
#include <cuda_fp16.h>
#include <math.h>

#define T_ 16
#define B_ 1024
#define F_DIM 512
#define H_ 128
#define L_ 512
#define C_ 100
#define FSPLIT 2
#define KSPLIT (T_ * FSPLIT)

// Scratch (static device globals -- no allocation allowed)
__device__ __nv_bfloat16 g_h[(size_t)T_ * B_ * H_];       // 4 MB
__device__ __nv_bfloat16 g_mu[(size_t)T_ * B_ * L_];      // 16 MB
__device__ unsigned g_lp[(size_t)T_ * (L_ / 2) * 128];    // 2 MB  packed leafp pairs
__device__ float g_part[(size_t)KSPLIT * B_ * C_];        // 13 MB
__device__ unsigned g_pf[(size_t)B_ * (F_DIM / 2)];       // 1 MB  packed feat pairs
__device__ unsigned g_pw1[(size_t)T_ * (F_DIM / 2) * H_]; // 2 MB  packed W1 pairs
__device__ unsigned g_pw2[(size_t)T_ * (H_ / 2) * L_];    // 2 MB  packed W2 pairs

__device__ __forceinline__ unsigned pkf(float lo, float hi) {
    __nv_bfloat162 h = __floats2bfloat162_rn(lo, hi);
    return *reinterpret_cast<unsigned*>(&h);
}

__device__ __forceinline__ void mma_bf16(float* d, const unsigned* a, const unsigned* b) {
    asm volatile(
        "mma.sync.aligned.m16n8k16.row.col.f32.bf16.bf16.f32 "
        "{%0,%1,%2,%3}, {%4,%5,%6,%7}, {%8,%9}, {%0,%1,%2,%3};\n"
        : "+f"(d[0]), "+f"(d[1]), "+f"(d[2]), "+f"(d[3])
        : "r"(a[0]), "r"(a[1]), "r"(a[2]), "r"(a[3]), "r"(b[0]), "r"(b[1]));
}

__device__ __forceinline__ void cp16(void* s, const void* g) {
    unsigned sa = (unsigned)__cvta_generic_to_shared(s);
    asm volatile("cp.async.ca.shared.global [%0], [%1], 16;\n" :: "r"(sa), "l"(g));
}
#define CP_COMMIT() asm volatile("cp.async.commit_group;\n")
#define CP_WAIT1()  asm volatile("cp.async.wait_group 1;\n")
#define CP_WAIT0()  asm volatile("cp.async.wait_group 0;\n")

// ---------------------------------------------------------------------------
// Pack feat / W1 / W2 into bf16x2 (pairs over k) MMA-ready layouts.
// grid (2048, 3) x 256 threads.
// ---------------------------------------------------------------------------
__global__ __launch_bounds__(256) void pack_inputs(const float* __restrict__ feat,
                                                   const float* __restrict__ W1,
                                                   const float* __restrict__ W2) {
    const int i = blockIdx.x * 256 + threadIdx.x;
    if (blockIdx.y == 0) {
        // g_pf[b][f2] = (feat[b][2f2], feat[b][2f2+1]); 262144 entries
        if (i < B_ * (F_DIM / 2)) {
            float2 v = *reinterpret_cast<const float2*>(&feat[(size_t)i * 2]);
            g_pf[i] = pkf(v.x, v.y);
        }
    } else if (blockIdx.y == 1) {
        // g_pw1[t][f2][n] = (W1[t][2f2][n], W1[t][2f2+1][n]); 524288 entries
        int t = i >> 15, rem = i & 32767, f2 = rem >> 7, n = rem & 127;
        const float* base = W1 + ((size_t)t * F_DIM + 2 * f2) * H_ + n;
        g_pw1[i] = pkf(base[0], base[H_]);
    } else {
        // g_pw2[t][h2][l] = (W2[t][2h2][l], W2[t][2h2+1][l]); 524288 entries
        int t = i >> 15, h2 = (i >> 9) & 63, l = i & 511;
        const float* base = W2 + ((size_t)t * H_ + 2 * h2) * L_ + l;
        g_pw2[i] = pkf(base[0], base[L_]);
    }
}

// ---------------------------------------------------------------------------
// Stage 1: h = relu(feat @ W1 + b1). 64x128 tile, BK=32, cp.async 2-stage.
// grid (B/64, 1, T) = 256 CTAs, 256 threads.
// ---------------------------------------------------------------------------
__global__ __launch_bounds__(256) void gemm1_bf16(const float* __restrict__ b1) {
    __shared__ unsigned As[2][64 * 20];
    __shared__ unsigned Bs[2][16 * 132];

    const int tid = threadIdx.x;
    const int wid = tid >> 5, lane = tid & 31;
    const int warp_m = wid >> 2, warp_n = wid & 3;
    const int lq = lane >> 2, lr = lane & 3;
    const int t = blockIdx.z;
    const int b0 = blockIdx.x * 64;

    const unsigned* pf = g_pf + (size_t)b0 * (F_DIM / 2);
    const unsigned* pw = g_pw1 + (size_t)t * (F_DIM / 2) * H_;
    const float* bb = b1 + (size_t)t * H_;

    float acc[2][4][4];
#pragma unroll
    for (int i = 0; i < 2; i++)
#pragma unroll
        for (int j = 0; j < 4; j++)
#pragma unroll
            for (int q = 0; q < 4; q++) acc[i][j][q] = 0.0f;

    auto issue = [&](int kt, int buf) {
        const int kp0 = kt * 16;
        // A: 64 rows x 4 uint4 chunks = 256 tasks, 1/thread
        {
            int r = tid >> 2, q = tid & 3;
            cp16(&As[buf][r * 20 + q * 4], &pf[(size_t)r * (F_DIM / 2) + kp0 + q * 4]);
        }
        // B: 16 pair-rows x 32 chunks (contiguous 512B rows), 2/thread
#pragma unroll
        for (int i = 0; i < 2; i++) {
            int e = tid + i * 256;
            int kp = e >> 5, c4 = e & 31;
            cp16(&Bs[buf][kp * 132 + c4 * 4], &pw[(size_t)(kp0 + kp) * H_ + c4 * 4]);
        }
        CP_COMMIT();
    };

    issue(0, 0);
#pragma unroll 1
    for (int kt = 0; kt < 16; kt++) {
        const int buf = kt & 1;
        if (kt < 15) { issue(kt + 1, buf ^ 1); CP_WAIT1(); } else { CP_WAIT0(); }
        __syncthreads();

#pragma unroll
        for (int kh = 0; kh < 2; kh++) {
            const int kb = kh * 8;
            unsigned afr[2][4], bfr[4][2];
#pragma unroll
            for (int im = 0; im < 2; im++) {
                int r = warp_m * 32 + im * 16;
                afr[im][0] = As[buf][(r + lq) * 20 + kb + lr];
                afr[im][1] = As[buf][(r + 8 + lq) * 20 + kb + lr];
                afr[im][2] = As[buf][(r + lq) * 20 + kb + 4 + lr];
                afr[im][3] = As[buf][(r + 8 + lq) * 20 + kb + 4 + lr];
            }
#pragma unroll
            for (int jn = 0; jn < 4; jn++) {
                int c = warp_n * 32 + jn * 8 + lq;
                bfr[jn][0] = Bs[buf][(kb + lr) * 132 + c];
                bfr[jn][1] = Bs[buf][(kb + 4 + lr) * 132 + c];
            }
#pragma unroll
            for (int im = 0; im < 2; im++)
#pragma unroll
                for (int jn = 0; jn < 4; jn++) mma_bf16(acc[im][jn], afr[im], bfr[jn]);
        }
        __syncthreads();
    }

    unsigned* gh = reinterpret_cast<unsigned*>(g_h);
#pragma unroll
    for (int im = 0; im < 2; im++) {
#pragma unroll
        for (int half = 0; half < 2; half++) {
            int r = warp_m * 32 + im * 16 + half * 8 + lq;
#pragma unroll
            for (int jn = 0; jn < 4; jn++) {
                int c = warp_n * 32 + jn * 8 + lr * 2;
                float x0 = fmaxf(acc[im][jn][half * 2 + 0] + bb[c], 0.0f);
                float x1 = fmaxf(acc[im][jn][half * 2 + 1] + bb[c + 1], 0.0f);
                gh[((size_t)t * B_ + b0 + r) * (H_ / 2) + (c >> 1)] = pkf(x0, x1);
            }
        }
    }
}

// ---------------------------------------------------------------------------
// Stage 2 fused: p = sigmoid(h @ W2 + b2) (staged fp16 smem) then mu routing
// products via tree-doubling -> bf16. 16 B-tiles (4 n-chunks x 4 k-steps)
// flattened into one cp.async double-buffered stream.
// grid (B/64, T) = 256 CTAs, 256 threads, ~99KB dyn smem.
// ---------------------------------------------------------------------------
#define SM2_HA (64 * 68)
#define SM2_BS (16 * 132)
#define SM2_BYTES ((SM2_HA + 2 * SM2_BS) * 4 + 64 * 520 * 2)

__global__ __launch_bounds__(256) void stage2_fused(const float* __restrict__ b2) {
    extern __shared__ unsigned smemu[];
    unsigned* hA = smemu;                                   // [64][68]
    unsigned* Bs0 = smemu + SM2_HA;                         // [2][16*132]
    __half* ph = reinterpret_cast<__half*>(smemu + SM2_HA + 2 * SM2_BS);  // [64][520]

    const int tid = threadIdx.x;
    const int wid = tid >> 5, lane = tid & 31;
    const int warp_m = wid >> 2, warp_n = wid & 3;
    const int lq = lane >> 2, lr = lane & 3;
    const int t = blockIdx.y;
    const int b0 = blockIdx.x * 64;

    // Load h tile (64 x 64 u32 pairs), resident.
    const unsigned* hsrc = reinterpret_cast<const unsigned*>(g_h) + ((size_t)t * B_ + b0) * (H_ / 2);
#pragma unroll
    for (int i = 0; i < 4; i++) {
        int e = tid + i * 256;
        int r = e >> 4, q = e & 15;
        cp16(&hA[r * 68 + q * 4], &hsrc[(size_t)r * 64 + q * 4]);
    }
    CP_COMMIT();

    const unsigned* pw = g_pw2 + (size_t)t * (H_ / 2) * L_;
    const float* bbt = b2 + (size_t)t * L_;

    auto issue = [&](int j, int buf) {
        const int chunk = j >> 2, k0s = j & 3;
        const unsigned* src = pw + (size_t)(k0s * 16) * L_ + chunk * 128;
#pragma unroll
        for (int i = 0; i < 2; i++) {
            int e = tid + i * 256;
            int kp = e >> 5, c4 = e & 31;
            cp16(&Bs0[buf * SM2_BS + kp * 132 + c4 * 4], &src[(size_t)kp * L_ + c4 * 4]);
        }
        CP_COMMIT();
    };

    issue(0, 0);   // group1; hA is group0 -- wait below covers both appropriately

    float acc[2][4][4];
#pragma unroll 1
    for (int j = 0; j < 16; j++) {
        const int chunk = j >> 2, k0s = j & 3, buf = j & 1;
        if (k0s == 0) {
#pragma unroll
            for (int i = 0; i < 2; i++)
#pragma unroll
                for (int jj = 0; jj < 4; jj++)
#pragma unroll
                    for (int q = 0; q < 4; q++) acc[i][jj][q] = 0.0f;
        }
        if (j < 15) { issue(j + 1, buf ^ 1); CP_WAIT1(); } else { CP_WAIT0(); }
        __syncthreads();

        const unsigned* Bs = Bs0 + buf * SM2_BS;
#pragma unroll
        for (int kh = 0; kh < 2; kh++) {
            const int kbG = k0s * 16 + kh * 8;
            const int kbB = kh * 8;
            unsigned afr[2][4], bfr[4][2];
#pragma unroll
            for (int im = 0; im < 2; im++) {
                int r = warp_m * 32 + im * 16;
                afr[im][0] = hA[(r + lq) * 68 + kbG + lr];
                afr[im][1] = hA[(r + 8 + lq) * 68 + kbG + lr];
                afr[im][2] = hA[(r + lq) * 68 + kbG + 4 + lr];
                afr[im][3] = hA[(r + 8 + lq) * 68 + kbG + 4 + lr];
            }
#pragma unroll
            for (int jn = 0; jn < 4; jn++) {
                int c = warp_n * 32 + jn * 8 + lq;
                bfr[jn][0] = Bs[(kbB + lr) * 132 + c];
                bfr[jn][1] = Bs[(kbB + 4 + lr) * 132 + c];
            }
#pragma unroll
            for (int im = 0; im < 2; im++)
#pragma unroll
                for (int jn = 0; jn < 4; jn++) mma_bf16(acc[im][jn], afr[im], bfr[jn]);
        }

        if (k0s == 3) {
            const int n0c = chunk * 128;
#pragma unroll
            for (int im = 0; im < 2; im++) {
#pragma unroll
                for (int half = 0; half < 2; half++) {
                    int r = warp_m * 32 + im * 16 + half * 8 + lq;
#pragma unroll
                    for (int jn = 0; jn < 4; jn++) {
                        int c = warp_n * 32 + jn * 8 + lr * 2;
                        float x0 = 1.0f / (1.0f + __expf(-(acc[im][jn][half * 2 + 0] + bbt[n0c + c])));
                        float x1 = 1.0f / (1.0f + __expf(-(acc[im][jn][half * 2 + 1] + bbt[n0c + c + 1])));
                        *reinterpret_cast<__half2*>(&ph[r * 520 + n0c + c]) = __floats2half2_rn(x0, x1);
                    }
                }
            }
        }
        __syncthreads();
    }

    // mu phase: 64 rows x 16 leaf-blocks = 1024 tasks, 4 per thread.
    unsigned* muout = reinterpret_cast<unsigned*>(g_mu) + ((size_t)t * B_ + b0) * (L_ / 2);
#pragma unroll 1
    for (int i = 0; i < 4; i++) {
        int task = i * 256 + tid;
        int row = task >> 4;
        int l0 = (task & 15) << 5;
        const __half* sp = ph + row * 520;

        float pref = 1.0f;
#pragma unroll
        for (int d = 0; d < 4; d++) {
            int node = (1 << d) - 1 + (l0 >> (9 - d));
            float v = __half2float(sp[node]);
            pref *= ((l0 >> (8 - d)) & 1) ? (1.0f - v) : v;
        }

        float cur[32];
        cur[0] = pref;
#pragma unroll
        for (int d = 4; d <= 8; d++) {
            const int width = 1 << (d - 4);
            const int nbase = (1 << d) - 1 + (l0 >> (9 - d));
#pragma unroll
            for (int ii = width - 1; ii >= 0; ii--) {
                float v = __half2float(sp[nbase + ii]);
                float x = cur[ii];
                cur[2 * ii] = x * v;
                cur[2 * ii + 1] = x * (1.0f - v);
            }
        }

        unsigned w[16];
#pragma unroll
        for (int j = 0; j < 16; j++) w[j] = pkf(cur[2 * j], cur[2 * j + 1]);
        unsigned* dst = muout + (size_t)row * (L_ / 2) + (l0 >> 1);
#pragma unroll
        for (int j4 = 0; j4 < 4; j4++)
            *reinterpret_cast<uint4*>(dst + j4 * 4) =
                *reinterpret_cast<uint4*>(&w[j4 * 4]);
    }
}

// ---------------------------------------------------------------------------
// Leaf softmax -> packed layout g_lp[t][l/2][128] (bf16x2 over l, zero-pad).
// ---------------------------------------------------------------------------
__global__ __launch_bounds__(128) void leaf_softmax_pack(const float* __restrict__ pi) {
    const int row = blockIdx.x * 4 + (threadIdx.x >> 5);   // t*L + l
    const int lane = threadIdx.x & 31;
    const int t = row >> 9, l = row & (L_ - 1);
    const float* pr = pi + (size_t)row * C_;

    float v[4];
#pragma unroll
    for (int j = 0; j < 4; j++) {
        int c = lane + j * 32;
        v[j] = (c < C_) ? pr[c] : -1e30f;
    }
    float m = fmaxf(fmaxf(v[0], v[1]), fmaxf(v[2], v[3]));
#pragma unroll
    for (int o = 16; o; o >>= 1) m = fmaxf(m, __shfl_xor_sync(0xffffffffu, m, o));

    float e[4];
    float s = 0.0f;
#pragma unroll
    for (int j = 0; j < 4; j++) {
        int c = lane + j * 32;
        e[j] = (c < C_) ? __expf(v[j] - m) : 0.0f;
        s += e[j];
    }
#pragma unroll
    for (int o = 16; o; o >>= 1) s += __shfl_xor_sync(0xffffffffu, s, o);
    float inv = 1.0f / s;

    unsigned short* base = reinterpret_cast<unsigned short*>(g_lp);
    const size_t rowbase = ((size_t)t * (L_ / 2) + (l >> 1)) * 128;
#pragma unroll
    for (int j = 0; j < 4; j++) {
        int c = lane + j * 32;
        __nv_bfloat16 bv = __float2bfloat16((c < C_) ? e[j] * inv : 0.0f);
        base[(rowbase + c) * 2 + (l & 1)] = *reinterpret_cast<unsigned short*>(&bv);
    }
}

// ---------------------------------------------------------------------------
// Final contraction: part[t*2+ks] = mu[t][:, ks*256:+256] @ leafp chunk.
// 128x128 tile, K=256 per CTA, cp.async double-buffered. grid (8, T, 2).
// ---------------------------------------------------------------------------
__global__ __launch_bounds__(256) void final_bf16() {
    __shared__ unsigned As[2][128 * 20];
    __shared__ unsigned Bs[2][16 * 132];

    const int tid = threadIdx.x;
    const int wid = tid >> 5, lane = tid & 31;
    const int warp_m = wid >> 2, warp_n = wid & 3;   // 2x4 warps, 64x32 warp tiles
    const int lq = lane >> 2, lr = lane & 3;
    const int t = blockIdx.y;
    const int ks = blockIdx.z;
    const int b0 = blockIdx.x * 128;

    const unsigned* mu_u = reinterpret_cast<const unsigned*>(g_mu) + ((size_t)t * B_ + b0) * (L_ / 2);
    const unsigned* lpb = g_lp + (size_t)t * (L_ / 2) * 128;

    float acc[4][4][4];
#pragma unroll
    for (int i = 0; i < 4; i++)
#pragma unroll
        for (int j = 0; j < 4; j++)
#pragma unroll
            for (int q = 0; q < 4; q++) acc[i][j][q] = 0.0f;

    auto issue = [&](int kt, int buf) {
        const int kp0 = (ks * 256 + kt * 32) >> 1;
#pragma unroll
        for (int i = 0; i < 2; i++) {
            int e = tid + i * 256;
            int r = e >> 2, q = e & 3;
            cp16(&As[buf][r * 20 + q * 4], &mu_u[(size_t)r * (L_ / 2) + kp0 + q * 4]);
        }
#pragma unroll
        for (int i = 0; i < 2; i++) {
            int e = tid + i * 256;
            int kp = e >> 5, c4 = e & 31;
            cp16(&Bs[buf][kp * 132 + c4 * 4], &lpb[(size_t)(kp0 + kp) * 128 + c4 * 4]);
        }
        CP_COMMIT();
    };

    issue(0, 0);
#pragma unroll 1
    for (int kt = 0; kt < 8; kt++) {
        const int buf = kt & 1;
        if (kt < 7) { issue(kt + 1, buf ^ 1); CP_WAIT1(); } else { CP_WAIT0(); }
        __syncthreads();

#pragma unroll
        for (int kh = 0; kh < 2; kh++) {
            const int kb = kh * 8;
            unsigned bfr[4][2];
#pragma unroll
            for (int jn = 0; jn < 4; jn++) {
                int c = warp_n * 32 + jn * 8 + lq;
                bfr[jn][0] = Bs[buf][(kb + lr) * 132 + c];
                bfr[jn][1] = Bs[buf][(kb + 4 + lr) * 132 + c];
            }
#pragma unroll
            for (int im = 0; im < 4; im++) {
                int r = warp_m * 64 + im * 16;
                unsigned afr[4];
                afr[0] = As[buf][(r + lq) * 20 + kb + lr];
                afr[1] = As[buf][(r + 8 + lq) * 20 + kb + lr];
                afr[2] = As[buf][(r + lq) * 20 + kb + 4 + lr];
                afr[3] = As[buf][(r + 8 + lq) * 20 + kb + 4 + lr];
#pragma unroll
                for (int jn = 0; jn < 4; jn++) mma_bf16(acc[im][jn], afr, bfr[jn]);
            }
        }
        __syncthreads();
    }

    float* pb = g_part + (size_t)(t * FSPLIT + ks) * B_ * C_;
#pragma unroll
    for (int im = 0; im < 4; im++) {
#pragma unroll
        for (int half = 0; half < 2; half++) {
            int r = warp_m * 64 + im * 16 + half * 8 + lq;
#pragma unroll
            for (int jn = 0; jn < 4; jn++) {
                int c = warp_n * 32 + jn * 8 + lr * 2;
                if (c >= C_) continue;
                *reinterpret_cast<float2*>(&pb[(size_t)(b0 + r) * C_ + c]) =
                    make_float2(acc[im][jn][half * 2 + 0], acc[im][jn][half * 2 + 1]);
            }
        }
    }
}

// ---------------------------------------------------------------------------
// Deterministic reduction over KSPLIT partials + final log
// ---------------------------------------------------------------------------
__global__ __launch_bounds__(256) void reduce_log_kernel(float* __restrict__ out) {
    const int i = blockIdx.x * 256 + threadIdx.x;
    float s = 0.0f;
#pragma unroll
    for (int ks = 0; ks < KSPLIT; ks++) s += g_part[(size_t)ks * B_ * C_ + i];
    out[i] = logf(s * (1.0f / (float)(L_ * T_)));
}

extern "C" void kernel_launch(void* const* d_in, const int* in_sizes, int n_in,
                              void* d_out, int out_size) {
    const float* feat = (const float*)d_in[0];
    const float* W1 = (const float*)d_in[1];
    const float* b1 = (const float*)d_in[2];
    const float* W2 = (const float*)d_in[3];
    const float* b2 = (const float*)d_in[4];
    const float* pi = (const float*)d_in[5];
    float* out = (float*)d_out;

    cudaFuncSetAttribute(stage2_fused, cudaFuncAttributeMaxDynamicSharedMemorySize, SM2_BYTES);

    pack_inputs<<<dim3(2048, 3), 256>>>(feat, W1, W2);
    leaf_softmax_pack<<<(T_ * L_) / 4, 128>>>(pi);
    gemm1_bf16<<<dim3(B_ / 64, 1, T_), 256>>>(b1);
    stage2_fused<<<dim3(B_ / 64, T_), 256, SM2_BYTES>>>(b2);
    final_bf16<<<dim3(B_ / 128, T_, FSPLIT), 256>>>();
    reduce_log_kernel<<<(B_ * C_) / 256, 256>>>(out);
}

// round 7
// speedup vs baseline: 1.2171x; 1.2171x over previous
#include <cuda_runtime.h>
#include <cuda_bf16.h>
#include <cuda_fp16.h>
#include <math.h>

#define T_ 16
#define B_ 1024
#define F_DIM 512
#define H_ 128
#define L_ 512
#define C_ 100
#define FSPLIT 2
#define KSPLIT (T_ * FSPLIT)

// Scratch (static device globals -- no allocation allowed)
__device__ __nv_bfloat16 g_h[(size_t)T_ * B_ * H_];       // 4 MB
__device__ __nv_bfloat16 g_mu[(size_t)T_ * B_ * L_];      // 16 MB
__device__ unsigned g_lp[(size_t)T_ * (L_ / 2) * 128];    // 2 MB  packed leafp pairs
__device__ float g_part[(size_t)KSPLIT * B_ * C_];        // 13 MB
__device__ unsigned g_pf[(size_t)B_ * (F_DIM / 2)];       // 1 MB  packed feat pairs
__device__ unsigned g_pw1[(size_t)T_ * (F_DIM / 2) * H_]; // 2 MB  packed W1 pairs
__device__ unsigned g_pw2[(size_t)T_ * (H_ / 2) * L_];    // 2 MB  packed W2 pairs

__device__ __forceinline__ unsigned pkf(float lo, float hi) {
    __nv_bfloat162 h = __floats2bfloat162_rn(lo, hi);
    return *reinterpret_cast<unsigned*>(&h);
}

__device__ __forceinline__ void mma_bf16(float* d, const unsigned* a, const unsigned* b) {
    asm volatile(
        "mma.sync.aligned.m16n8k16.row.col.f32.bf16.bf16.f32 "
        "{%0,%1,%2,%3}, {%4,%5,%6,%7}, {%8,%9}, {%0,%1,%2,%3};\n"
        : "+f"(d[0]), "+f"(d[1]), "+f"(d[2]), "+f"(d[3])
        : "r"(a[0]), "r"(a[1]), "r"(a[2]), "r"(a[3]), "r"(b[0]), "r"(b[1]));
}

__device__ __forceinline__ void cp16(void* s, const void* g) {
    unsigned sa = (unsigned)__cvta_generic_to_shared(s);
    asm volatile("cp.async.ca.shared.global [%0], [%1], 16;\n" :: "r"(sa), "l"(g));
}
#define CP_COMMIT() asm volatile("cp.async.commit_group;\n")
#define CP_WAIT1()  asm volatile("cp.async.wait_group 1;\n")
#define CP_WAIT0()  asm volatile("cp.async.wait_group 0;\n")

// ---------------------------------------------------------------------------
// Pack feat / W1 / W2 into bf16x2 (pairs over k) MMA-ready layouts.
// ---------------------------------------------------------------------------
__global__ __launch_bounds__(256) void pack_inputs(const float* __restrict__ feat,
                                                   const float* __restrict__ W1,
                                                   const float* __restrict__ W2) {
    const int i = blockIdx.x * 256 + threadIdx.x;
    if (blockIdx.y == 0) {
        if (i < B_ * (F_DIM / 2)) {
            float2 v = *reinterpret_cast<const float2*>(&feat[(size_t)i * 2]);
            g_pf[i] = pkf(v.x, v.y);
        }
    } else if (blockIdx.y == 1) {
        int t = i >> 15, rem = i & 32767, f2 = rem >> 7, n = rem & 127;
        const float* base = W1 + ((size_t)t * F_DIM + 2 * f2) * H_ + n;
        g_pw1[i] = pkf(base[0], base[H_]);
    } else {
        int t = i >> 15, h2 = (i >> 9) & 63, l = i & 511;
        const float* base = W2 + ((size_t)t * H_ + 2 * h2) * L_ + l;
        g_pw2[i] = pkf(base[0], base[L_]);
    }
}

// ---------------------------------------------------------------------------
// Stage 1: h = relu(feat @ W1 + b1). 64x128 tile, BK=32, cp.async 2-stage.
// grid (B/64, 1, T) = 256 CTAs, 256 threads.
// ---------------------------------------------------------------------------
__global__ __launch_bounds__(256) void gemm1_bf16(const float* __restrict__ b1) {
    __shared__ unsigned As[2][64 * 20];
    __shared__ unsigned Bs[2][16 * 132];

    const int tid = threadIdx.x;
    const int wid = tid >> 5, lane = tid & 31;
    const int warp_m = wid >> 2, warp_n = wid & 3;
    const int lq = lane >> 2, lr = lane & 3;
    const int t = blockIdx.z;
    const int b0 = blockIdx.x * 64;

    const unsigned* pf = g_pf + (size_t)b0 * (F_DIM / 2);
    const unsigned* pw = g_pw1 + (size_t)t * (F_DIM / 2) * H_;
    const float* bb = b1 + (size_t)t * H_;

    float acc[2][4][4];
#pragma unroll
    for (int i = 0; i < 2; i++)
#pragma unroll
        for (int j = 0; j < 4; j++)
#pragma unroll
            for (int q = 0; q < 4; q++) acc[i][j][q] = 0.0f;

    auto issue = [&](int kt, int buf) {
        const int kp0 = kt * 16;
        {
            int r = tid >> 2, q = tid & 3;
            cp16(&As[buf][r * 20 + q * 4], &pf[(size_t)r * (F_DIM / 2) + kp0 + q * 4]);
        }
#pragma unroll
        for (int i = 0; i < 2; i++) {
            int e = tid + i * 256;
            int kp = e >> 5, c4 = e & 31;
            cp16(&Bs[buf][kp * 132 + c4 * 4], &pw[(size_t)(kp0 + kp) * H_ + c4 * 4]);
        }
        CP_COMMIT();
    };

    issue(0, 0);
#pragma unroll 1
    for (int kt = 0; kt < 16; kt++) {
        const int buf = kt & 1;
        if (kt < 15) { issue(kt + 1, buf ^ 1); CP_WAIT1(); } else { CP_WAIT0(); }
        __syncthreads();

#pragma unroll
        for (int kh = 0; kh < 2; kh++) {
            const int kb = kh * 8;
            unsigned afr[2][4], bfr[4][2];
#pragma unroll
            for (int im = 0; im < 2; im++) {
                int r = warp_m * 32 + im * 16;
                afr[im][0] = As[buf][(r + lq) * 20 + kb + lr];
                afr[im][1] = As[buf][(r + 8 + lq) * 20 + kb + lr];
                afr[im][2] = As[buf][(r + lq) * 20 + kb + 4 + lr];
                afr[im][3] = As[buf][(r + 8 + lq) * 20 + kb + 4 + lr];
            }
#pragma unroll
            for (int jn = 0; jn < 4; jn++) {
                int c = warp_n * 32 + jn * 8 + lq;
                bfr[jn][0] = Bs[buf][(kb + lr) * 132 + c];
                bfr[jn][1] = Bs[buf][(kb + 4 + lr) * 132 + c];
            }
#pragma unroll
            for (int im = 0; im < 2; im++)
#pragma unroll
                for (int jn = 0; jn < 4; jn++) mma_bf16(acc[im][jn], afr[im], bfr[jn]);
        }
        __syncthreads();
    }

    unsigned* gh = reinterpret_cast<unsigned*>(g_h);
#pragma unroll
    for (int im = 0; im < 2; im++) {
#pragma unroll
        for (int half = 0; half < 2; half++) {
            int r = warp_m * 32 + im * 16 + half * 8 + lq;
#pragma unroll
            for (int jn = 0; jn < 4; jn++) {
                int c = warp_n * 32 + jn * 8 + lr * 2;
                float x0 = fmaxf(acc[im][jn][half * 2 + 0] + bb[c], 0.0f);
                float x1 = fmaxf(acc[im][jn][half * 2 + 1] + bb[c + 1], 0.0f);
                gh[((size_t)t * B_ + b0 + r) * (H_ / 2) + (c >> 1)] = pkf(x0, x1);
            }
        }
    }
}

// ---------------------------------------------------------------------------
// Stage 2 fused: p = sigmoid(h @ W2 + b2) (staged fp16 smem) then mu routing
// products. mu uses 16-leaf subtrees per task (cur[16] -- fits registers, no
// local-memory spill). grid (B/64, T) = 256 CTAs, 256 threads.
// ---------------------------------------------------------------------------
#define SM2_HA (64 * 68)
#define SM2_BS (16 * 132)
#define SM2_BYTES ((SM2_HA + 2 * SM2_BS) * 4 + 64 * 520 * 2)

__global__ __launch_bounds__(256) void stage2_fused(const float* __restrict__ b2) {
    extern __shared__ unsigned smemu[];
    unsigned* hA = smemu;                                   // [64][68]
    unsigned* Bs0 = smemu + SM2_HA;                         // [2][16*132]
    __half* ph = reinterpret_cast<__half*>(smemu + SM2_HA + 2 * SM2_BS);  // [64][520]

    const int tid = threadIdx.x;
    const int wid = tid >> 5, lane = tid & 31;
    const int warp_m = wid >> 2, warp_n = wid & 3;
    const int lq = lane >> 2, lr = lane & 3;
    const int t = blockIdx.y;
    const int b0 = blockIdx.x * 64;

    const unsigned* hsrc = reinterpret_cast<const unsigned*>(g_h) + ((size_t)t * B_ + b0) * (H_ / 2);
#pragma unroll
    for (int i = 0; i < 4; i++) {
        int e = tid + i * 256;
        int r = e >> 4, q = e & 15;
        cp16(&hA[r * 68 + q * 4], &hsrc[(size_t)r * 64 + q * 4]);
    }
    CP_COMMIT();

    const unsigned* pw = g_pw2 + (size_t)t * (H_ / 2) * L_;
    const float* bbt = b2 + (size_t)t * L_;

    auto issue = [&](int j, int buf) {
        const int chunk = j >> 2, k0s = j & 3;
        const unsigned* src = pw + (size_t)(k0s * 16) * L_ + chunk * 128;
#pragma unroll
        for (int i = 0; i < 2; i++) {
            int e = tid + i * 256;
            int kp = e >> 5, c4 = e & 31;
            cp16(&Bs0[buf * SM2_BS + kp * 132 + c4 * 4], &src[(size_t)kp * L_ + c4 * 4]);
        }
        CP_COMMIT();
    };

    issue(0, 0);

    float acc[2][4][4];
#pragma unroll 1
    for (int j = 0; j < 16; j++) {
        const int chunk = j >> 2, k0s = j & 3, buf = j & 1;
        if (k0s == 0) {
#pragma unroll
            for (int i = 0; i < 2; i++)
#pragma unroll
                for (int jj = 0; jj < 4; jj++)
#pragma unroll
                    for (int q = 0; q < 4; q++) acc[i][jj][q] = 0.0f;
        }
        if (j < 15) { issue(j + 1, buf ^ 1); CP_WAIT1(); } else { CP_WAIT0(); }
        __syncthreads();

        const unsigned* Bs = Bs0 + buf * SM2_BS;
#pragma unroll
        for (int kh = 0; kh < 2; kh++) {
            const int kbG = k0s * 16 + kh * 8;
            const int kbB = kh * 8;
            unsigned afr[2][4], bfr[4][2];
#pragma unroll
            for (int im = 0; im < 2; im++) {
                int r = warp_m * 32 + im * 16;
                afr[im][0] = hA[(r + lq) * 68 + kbG + lr];
                afr[im][1] = hA[(r + 8 + lq) * 68 + kbG + lr];
                afr[im][2] = hA[(r + lq) * 68 + kbG + 4 + lr];
                afr[im][3] = hA[(r + 8 + lq) * 68 + kbG + 4 + lr];
            }
#pragma unroll
            for (int jn = 0; jn < 4; jn++) {
                int c = warp_n * 32 + jn * 8 + lq;
                bfr[jn][0] = Bs[(kbB + lr) * 132 + c];
                bfr[jn][1] = Bs[(kbB + 4 + lr) * 132 + c];
            }
#pragma unroll
            for (int im = 0; im < 2; im++)
#pragma unroll
                for (int jn = 0; jn < 4; jn++) mma_bf16(acc[im][jn], afr[im], bfr[jn]);
        }

        if (k0s == 3) {
            const int n0c = chunk * 128;
#pragma unroll
            for (int im = 0; im < 2; im++) {
#pragma unroll
                for (int half = 0; half < 2; half++) {
                    int r = warp_m * 32 + im * 16 + half * 8 + lq;
#pragma unroll
                    for (int jn = 0; jn < 4; jn++) {
                        int c = warp_n * 32 + jn * 8 + lr * 2;
                        float x0 = 1.0f / (1.0f + __expf(-(acc[im][jn][half * 2 + 0] + bbt[n0c + c])));
                        float x1 = 1.0f / (1.0f + __expf(-(acc[im][jn][half * 2 + 1] + bbt[n0c + c + 1])));
                        *reinterpret_cast<__half2*>(&ph[r * 520 + n0c + c]) = __floats2half2_rn(x0, x1);
                    }
                }
            }
        }
        __syncthreads();
    }

    // mu phase: 64 rows x 32 subtrees (16 leaves each) = 2048 tasks, 8/thread.
    // cur[16] stays in registers (fully static indices after unroll).
    unsigned* muout = reinterpret_cast<unsigned*>(g_mu) + ((size_t)t * B_ + b0) * (L_ / 2);
#pragma unroll 1
    for (int i = 0; i < 8; i++) {
        int task = i * 256 + tid;
        int row = task >> 5;
        int s = task & 31;
        int l0 = s << 4;
        const __half* sp = ph + row * 520;

        float pref = 1.0f;
#pragma unroll
        for (int d = 0; d < 5; d++) {
            int node = (1 << d) - 1 + (l0 >> (9 - d));
            float v = __half2float(sp[node]);
            pref *= ((l0 >> (8 - d)) & 1) ? (1.0f - v) : v;
        }

        float cur[16];
        cur[0] = pref;
#pragma unroll
        for (int d = 5; d <= 8; d++) {
            const int width = 1 << (d - 5);
            const int nbase = (1 << d) - 1 + (l0 >> (9 - d));
#pragma unroll
            for (int ii = width - 1; ii >= 0; ii--) {
                float v = __half2float(sp[nbase + ii]);
                float x = cur[ii];
                cur[2 * ii] = x * v;
                cur[2 * ii + 1] = x * (1.0f - v);
            }
        }

        unsigned w[8];
#pragma unroll
        for (int jj = 0; jj < 8; jj++) w[jj] = pkf(cur[2 * jj], cur[2 * jj + 1]);
        unsigned* dst = muout + (size_t)row * (L_ / 2) + s * 8;
        *reinterpret_cast<uint4*>(dst) = *reinterpret_cast<uint4*>(&w[0]);
        *reinterpret_cast<uint4*>(dst + 4) = *reinterpret_cast<uint4*>(&w[4]);
    }
}

// ---------------------------------------------------------------------------
// Leaf softmax -> packed layout g_lp[t][l/2][128] (bf16x2 over l, zero-pad).
// ---------------------------------------------------------------------------
__global__ __launch_bounds__(128) void leaf_softmax_pack(const float* __restrict__ pi) {
    const int row = blockIdx.x * 4 + (threadIdx.x >> 5);   // t*L + l
    const int lane = threadIdx.x & 31;
    const int t = row >> 9, l = row & (L_ - 1);
    const float* pr = pi + (size_t)row * C_;

    float v[4];
#pragma unroll
    for (int j = 0; j < 4; j++) {
        int c = lane + j * 32;
        v[j] = (c < C_) ? pr[c] : -1e30f;
    }
    float m = fmaxf(fmaxf(v[0], v[1]), fmaxf(v[2], v[3]));
#pragma unroll
    for (int o = 16; o; o >>= 1) m = fmaxf(m, __shfl_xor_sync(0xffffffffu, m, o));

    float e[4];
    float s = 0.0f;
#pragma unroll
    for (int j = 0; j < 4; j++) {
        int c = lane + j * 32;
        e[j] = (c < C_) ? __expf(v[j] - m) : 0.0f;
        s += e[j];
    }
#pragma unroll
    for (int o = 16; o; o >>= 1) s += __shfl_xor_sync(0xffffffffu, s, o);
    float inv = 1.0f / s;

    unsigned short* base = reinterpret_cast<unsigned short*>(g_lp);
    const size_t rowbase = ((size_t)t * (L_ / 2) + (l >> 1)) * 128;
#pragma unroll
    for (int j = 0; j < 4; j++) {
        int c = lane + j * 32;
        __nv_bfloat16 bv = __float2bfloat16((c < C_) ? e[j] * inv : 0.0f);
        base[(rowbase + c) * 2 + (l & 1)] = *reinterpret_cast<unsigned short*>(&bv);
    }
}

// ---------------------------------------------------------------------------
// Final contraction: part[t*2+ks] = mu[t][:, ks*256:+256] @ leafp chunk.
// 128x128 tile, K=256 per CTA, cp.async double-buffered. grid (8, T, 2).
// ---------------------------------------------------------------------------
__global__ __launch_bounds__(256) void final_bf16() {
    __shared__ unsigned As[2][128 * 20];
    __shared__ unsigned Bs[2][16 * 132];

    const int tid = threadIdx.x;
    const int wid = tid >> 5, lane = tid & 31;
    const int warp_m = wid >> 2, warp_n = wid & 3;
    const int lq = lane >> 2, lr = lane & 3;
    const int t = blockIdx.y;
    const int ks = blockIdx.z;
    const int b0 = blockIdx.x * 128;

    const unsigned* mu_u = reinterpret_cast<const unsigned*>(g_mu) + ((size_t)t * B_ + b0) * (L_ / 2);
    const unsigned* lpb = g_lp + (size_t)t * (L_ / 2) * 128;

    float acc[4][4][4];
#pragma unroll
    for (int i = 0; i < 4; i++)
#pragma unroll
        for (int j = 0; j < 4; j++)
#pragma unroll
            for (int q = 0; q < 4; q++) acc[i][j][q] = 0.0f;

    auto issue = [&](int kt, int buf) {
        const int kp0 = (ks * 256 + kt * 32) >> 1;
#pragma unroll
        for (int i = 0; i < 2; i++) {
            int e = tid + i * 256;
            int r = e >> 2, q = e & 3;
            cp16(&As[buf][r * 20 + q * 4], &mu_u[(size_t)r * (L_ / 2) + kp0 + q * 4]);
        }
#pragma unroll
        for (int i = 0; i < 2; i++) {
            int e = tid + i * 256;
            int kp = e >> 5, c4 = e & 31;
            cp16(&Bs[buf][kp * 132 + c4 * 4], &lpb[(size_t)(kp0 + kp) * 128 + c4 * 4]);
        }
        CP_COMMIT();
    };

    issue(0, 0);
#pragma unroll 1
    for (int kt = 0; kt < 8; kt++) {
        const int buf = kt & 1;
        if (kt < 7) { issue(kt + 1, buf ^ 1); CP_WAIT1(); } else { CP_WAIT0(); }
        __syncthreads();

#pragma unroll
        for (int kh = 0; kh < 2; kh++) {
            const int kb = kh * 8;
            unsigned bfr[4][2];
#pragma unroll
            for (int jn = 0; jn < 4; jn++) {
                int c = warp_n * 32 + jn * 8 + lq;
                bfr[jn][0] = Bs[buf][(kb + lr) * 132 + c];
                bfr[jn][1] = Bs[buf][(kb + 4 + lr) * 132 + c];
            }
#pragma unroll
            for (int im = 0; im < 4; im++) {
                int r = warp_m * 64 + im * 16;
                unsigned afr[4];
                afr[0] = As[buf][(r + lq) * 20 + kb + lr];
                afr[1] = As[buf][(r + 8 + lq) * 20 + kb + lr];
                afr[2] = As[buf][(r + lq) * 20 + kb + 4 + lr];
                afr[3] = As[buf][(r + 8 + lq) * 20 + kb + 4 + lr];
#pragma unroll
                for (int jn = 0; jn < 4; jn++) mma_bf16(acc[im][jn], afr, bfr[jn]);
            }
        }
        __syncthreads();
    }

    float* pb = g_part + (size_t)(t * FSPLIT + ks) * B_ * C_;
#pragma unroll
    for (int im = 0; im < 4; im++) {
#pragma unroll
        for (int half = 0; half < 2; half++) {
            int r = warp_m * 64 + im * 16 + half * 8 + lq;
#pragma unroll
            for (int jn = 0; jn < 4; jn++) {
                int c = warp_n * 32 + jn * 8 + lr * 2;
                if (c >= C_) continue;
                *reinterpret_cast<float2*>(&pb[(size_t)(b0 + r) * C_ + c]) =
                    make_float2(acc[im][jn][half * 2 + 0], acc[im][jn][half * 2 + 1]);
            }
        }
    }
}

// ---------------------------------------------------------------------------
// Deterministic reduction over KSPLIT partials + final log
// ---------------------------------------------------------------------------
__global__ __launch_bounds__(256) void reduce_log_kernel(float* __restrict__ out) {
    const int i = blockIdx.x * 256 + threadIdx.x;
    float s = 0.0f;
#pragma unroll
    for (int ks = 0; ks < KSPLIT; ks++) s += g_part[(size_t)ks * B_ * C_ + i];
    out[i] = logf(s * (1.0f / (float)(L_ * T_)));
}

extern "C" void kernel_launch(void* const* d_in, const int* in_sizes, int n_in,
                              void* d_out, int out_size) {
    const float* feat = (const float*)d_in[0];
    const float* W1 = (const float*)d_in[1];
    const float* b1 = (const float*)d_in[2];
    const float* W2 = (const float*)d_in[3];
    const float* b2 = (const float*)d_in[4];
    const float* pi = (const float*)d_in[5];
    float* out = (float*)d_out;

    cudaFuncSetAttribute(stage2_fused, cudaFuncAttributeMaxDynamicSharedMemorySize, SM2_BYTES);

    pack_inputs<<<dim3(2048, 3), 256>>>(feat, W1, W2);
    leaf_softmax_pack<<<(T_ * L_) / 4, 128>>>(pi);
    gemm1_bf16<<<dim3(B_ / 64, 1, T_), 256>>>(b1);
    stage2_fused<<<dim3(B_ / 64, T_), 256, SM2_BYTES>>>(b2);
    final_bf16<<<dim3(B_ / 128, T_, FSPLIT), 256>>>();
    reduce_log_kernel<<<(B_ * C_) / 256, 256>>>(out);
}